// round 16
// baseline (speedup 1.0000x reference)
#include <cuda_runtime.h>
#include <math.h>

// L=2, H=1024, HM=256, E=64, B=64, T=256, D=1024
// rows = B*T = 16384, 4H = 4096, 4HM = 1024, D+H = 2048, recur main K=1024, meta K=1280

typedef unsigned long long u64;

// ---------------- packed f32x2 helpers (Blackwell FFMA2) ----------------
__device__ __forceinline__ u64 splat2(float x) {
    u64 r; unsigned xi = __float_as_uint(x);
    asm("mov.b64 %0, {%1, %1};" : "=l"(r) : "r"(xi));
    return r;
}
__device__ __forceinline__ u64 ffma2(u64 a, u64 b, u64 c) {
    u64 d;
    asm("fma.rn.f32x2 %0, %1, %2, %3;" : "=l"(d) : "l"(a), "l"(b), "l"(c));
    return d;
}
__device__ __forceinline__ u64 fadd2(u64 a, u64 b) {
    u64 d;
    asm("add.rn.f32x2 %0, %1, %2;" : "=l"(d) : "l"(a), "l"(b));
    return d;
}

// ---------------- scratch (__device__ globals, allowed) ----------------
__device__ float g_Gx[16384L * 4096];      // gx precompute [b*T+t][4096]
__device__ float g_Mx[16384L * 1024];      // x-part of mpre (+bm) [b*T+t][1024]
__device__ float g_X1[16384L * 1024];      // layer-0 output
__device__ float g_Wpack[1024L * 1280];    // packed [Wmx_h | Wmh] as [n][1280]
__device__ float g_Acat[64 * 1280];        // per-batch [h(1024) | mh(256)]
__device__ float g_c[64 * 1024];           // main cell
__device__ float g_mc[64 * 256];           // meta cell
__device__ float g_mpart[16L * 64 * 1024]; // meta GEMM K-split partials (16)
__device__ float g_gpart[16L * 64 * 4096]; // main GEMM K-split partials (16)
__device__ float g_z[3L * 64 * 256];       // z [s][b][g*64+e]
__device__ float g_d[3L * 64 * 4096];      // d [s][b][g*1024+h]

__device__ unsigned g_cnt = 0;
__device__ volatile unsigned g_gen = 0;
__device__ unsigned g_q[2];                // ping-pong work queues for phase A

__device__ __forceinline__ float sigf(float x) { return 1.0f / (1.0f + expf(-x)); }

// sense-reversing grid barrier (all 148 blocks resident — safe)
__device__ __forceinline__ void gridbar(unsigned nb, unsigned& sense)
{
    __syncthreads();
    if (threadIdx.x == 0) {
        __threadfence();
        unsigned a = atomicAdd(&g_cnt, 1u);
        if (a == nb - 1u) {
            g_cnt = 0;
            __threadfence();
            g_gen = sense + 1u;
        } else {
            while (g_gen != sense + 1u) { __nanosleep(32); }
        }
        __threadfence();
    }
    sense += 1u;
    __syncthreads();
}

#define BARG(id) asm volatile("bar.sync %0, 128;" :: "r"(id) : "memory")

// ---------------- big precompute SGEMM (f32x2): C[16384,N] = A @ W^T (+bias) ----
// 128x128 tile, 8x8 per thread (acc pairs along n), double-buffered
__global__ __launch_bounds__(256, 2) void sgemm128(
    const float* __restrict__ A, const float* __restrict__ W, int ldw,
    const float* __restrict__ bias, float* __restrict__ C, int N)
{
    __shared__ float As[2][8][132];
    __shared__ float Ws[2][8][132];
    int tid  = threadIdx.x;
    int m0   = blockIdx.y * 128;
    int n0   = blockIdx.x * 128;
    int lrow = tid >> 1;
    int lk4  = (tid & 1) * 4;
    const float* Aload = A + (long)(m0 + lrow) * 1024 + lk4;
    const float* Wload = W + (long)(n0 + lrow) * ldw + lk4;
    int tr = (tid >> 4) * 8;
    int tc = (tid & 15) * 8;

    u64 acc[8][4];
#pragma unroll
    for (int i = 0; i < 8; i++)
#pragma unroll
        for (int j = 0; j < 4; j++) acc[i][j] = 0ULL;

    float4 ra = *(const float4*)(Aload);
    float4 rw = *(const float4*)(Wload);
    As[0][lk4 + 0][lrow] = ra.x; As[0][lk4 + 1][lrow] = ra.y;
    As[0][lk4 + 2][lrow] = ra.z; As[0][lk4 + 3][lrow] = ra.w;
    Ws[0][lk4 + 0][lrow] = rw.x; Ws[0][lk4 + 1][lrow] = rw.y;
    Ws[0][lk4 + 2][lrow] = rw.z; Ws[0][lk4 + 3][lrow] = rw.w;
    __syncthreads();

    for (int c = 0; c < 128; c++) {               // 1024 / 8 chunks
        if (c < 127) {
            ra = *(const float4*)(Aload + (c + 1) * 8);
            rw = *(const float4*)(Wload + (c + 1) * 8);
        }
        int buf = c & 1;
#pragma unroll
        for (int k = 0; k < 8; k++) {
            float4 a0 = *(const float4*)&As[buf][k][tr];
            float4 a1 = *(const float4*)&As[buf][k][tr + 4];
            u64 s0 = splat2(a0.x), s1 = splat2(a0.y), s2 = splat2(a0.z), s3 = splat2(a0.w);
            u64 s4 = splat2(a1.x), s5 = splat2(a1.y), s6 = splat2(a1.z), s7 = splat2(a1.w);
            ulonglong2 w01 = *(const ulonglong2*)&Ws[buf][k][tc];
            ulonglong2 w23 = *(const ulonglong2*)&Ws[buf][k][tc + 4];
            u64 sa[8] = {s0, s1, s2, s3, s4, s5, s6, s7};
#pragma unroll
            for (int i = 0; i < 8; i++) {
                acc[i][0] = ffma2(sa[i], w01.x, acc[i][0]);
                acc[i][1] = ffma2(sa[i], w01.y, acc[i][1]);
                acc[i][2] = ffma2(sa[i], w23.x, acc[i][2]);
                acc[i][3] = ffma2(sa[i], w23.y, acc[i][3]);
            }
        }
        if (c < 127) {
            int nb2 = (c + 1) & 1;
            As[nb2][lk4 + 0][lrow] = ra.x; As[nb2][lk4 + 1][lrow] = ra.y;
            As[nb2][lk4 + 2][lrow] = ra.z; As[nb2][lk4 + 3][lrow] = ra.w;
            Ws[nb2][lk4 + 0][lrow] = rw.x; Ws[nb2][lk4 + 1][lrow] = rw.y;
            Ws[nb2][lk4 + 2][lrow] = rw.z; Ws[nb2][lk4 + 3][lrow] = rw.w;
        }
        __syncthreads();
    }
#pragma unroll
    for (int i = 0; i < 8; i++) {
        float* cp = C + (long)(m0 + tr + i) * N + n0 + tc;
        u64 v0 = acc[i][0], v1 = acc[i][1], v2 = acc[i][2], v3 = acc[i][3];
        if (bias) {
            v0 = fadd2(v0, *(const u64*)&bias[n0 + tc + 0]);
            v1 = fadd2(v1, *(const u64*)&bias[n0 + tc + 2]);
            v2 = fadd2(v2, *(const u64*)&bias[n0 + tc + 4]);
            v3 = fadd2(v3, *(const u64*)&bias[n0 + tc + 6]);
        }
        ulonglong2 st0; st0.x = v0; st0.y = v1;
        ulonglong2 st1; st1.x = v2; st1.y = v3;
        *(ulonglong2*)(cp)     = st0;
        *(ulonglong2*)(cp + 4) = st1;
    }
}

// ---------------- pack [Wmx_h | Wmh] into k-contiguous [n][1280] ----------
__global__ void pack_meta(const float* __restrict__ Wmx_l, const float* __restrict__ Wmh_l)
{
    int idx = blockIdx.x * 256 + threadIdx.x;
    if (idx >= 1024 * 1280) return;
    int n = idx / 1280;
    int k = idx - n * 1280;
    g_Wpack[idx] = (k < 1024) ? Wmx_l[n * 2048 + 1024 + k]
                              : Wmh_l[n * 256 + (k - 1024)];
}

// ---------------- phase A: 64b x 128n tile, 128-thread warpgroup, f32x2 -----------
// Cp[kyIdx][64,N] = Acat[64, ky..ky+Ksub) @ W[N,ldw]^T ; chunk 8, double-buffered
__device__ __forceinline__ void skinnyA(
    const float* __restrict__ W, int ldw,
    float* __restrict__ Cp, int N, int Ksub, int n0, int kyIdx,
    float* sm, int gtid, int barid)
{
    int ky   = kyIdx * Ksub;
    int arow = gtid >> 1;
    int ak   = (gtid & 1) * 4;
    const float* Aload = g_Acat + arow * 1280 + ky + ak;
    const float* Wload = W + (long)(n0 + gtid) * ldw + ky;
    int tb = ((gtid >> 4) & 7) * 8;
    int tc = (gtid & 15) * 8;

    u64 acc[8][4];
#pragma unroll
    for (int i = 0; i < 8; i++)
#pragma unroll
        for (int j = 0; j < 4; j++) acc[i][j] = 0ULL;

    int nch = Ksub >> 3;
    float4 pa  = *(const float4*)(Aload);
    float4 pw0 = *(const float4*)(Wload);
    float4 pw1 = *(const float4*)(Wload + 4);
    {
        float* As = sm; float* Ws = sm + 544;
        As[(ak + 0) * 68 + arow] = pa.x; As[(ak + 1) * 68 + arow] = pa.y;
        As[(ak + 2) * 68 + arow] = pa.z; As[(ak + 3) * 68 + arow] = pa.w;
        Ws[0 * 128 + gtid] = pw0.x; Ws[1 * 128 + gtid] = pw0.y;
        Ws[2 * 128 + gtid] = pw0.z; Ws[3 * 128 + gtid] = pw0.w;
        Ws[4 * 128 + gtid] = pw1.x; Ws[5 * 128 + gtid] = pw1.y;
        Ws[6 * 128 + gtid] = pw1.z; Ws[7 * 128 + gtid] = pw1.w;
    }
    BARG(barid);

    for (int c = 0; c < nch; c++) {
        if (c + 1 < nch) {
            pa  = *(const float4*)(Aload + (c + 1) * 8);
            pw0 = *(const float4*)(Wload + (c + 1) * 8);
            pw1 = *(const float4*)(Wload + (c + 1) * 8 + 4);
        }
        float* As = sm + (c & 1) * 1568;
        float* Ws = As + 544;
#pragma unroll
        for (int k = 0; k < 8; k++) {
            float4 a0 = *(const float4*)&As[k * 68 + tb];
            float4 a1 = *(const float4*)&As[k * 68 + tb + 4];
            u64 sa[8];
            sa[0] = splat2(a0.x); sa[1] = splat2(a0.y); sa[2] = splat2(a0.z); sa[3] = splat2(a0.w);
            sa[4] = splat2(a1.x); sa[5] = splat2(a1.y); sa[6] = splat2(a1.z); sa[7] = splat2(a1.w);
            ulonglong2 w01 = *(const ulonglong2*)&Ws[k * 128 + tc];
            ulonglong2 w23 = *(const ulonglong2*)&Ws[k * 128 + tc + 4];
#pragma unroll
            for (int i = 0; i < 8; i++) {
                acc[i][0] = ffma2(sa[i], w01.x, acc[i][0]);
                acc[i][1] = ffma2(sa[i], w01.y, acc[i][1]);
                acc[i][2] = ffma2(sa[i], w23.x, acc[i][2]);
                acc[i][3] = ffma2(sa[i], w23.y, acc[i][3]);
            }
        }
        if (c + 1 < nch) {
            float* An = sm + ((c + 1) & 1) * 1568;
            float* Wn = An + 544;
            An[(ak + 0) * 68 + arow] = pa.x; An[(ak + 1) * 68 + arow] = pa.y;
            An[(ak + 2) * 68 + arow] = pa.z; An[(ak + 3) * 68 + arow] = pa.w;
            Wn[0 * 128 + gtid] = pw0.x; Wn[1 * 128 + gtid] = pw0.y;
            Wn[2 * 128 + gtid] = pw0.z; Wn[3 * 128 + gtid] = pw0.w;
            Wn[4 * 128 + gtid] = pw1.x; Wn[5 * 128 + gtid] = pw1.y;
            Wn[6 * 128 + gtid] = pw1.z; Wn[7 * 128 + gtid] = pw1.w;
        }
        BARG(barid);
    }
#pragma unroll
    for (int i = 0; i < 8; i++) {
        float* cp = Cp + ((long)kyIdx * 64 + tb + i) * N + n0 + tc;
        ulonglong2 st0; st0.x = acc[i][0]; st0.y = acc[i][1];
        ulonglong2 st1; st1.x = acc[i][2]; st1.y = acc[i][3];
        *(ulonglong2*)(cp)     = st0;
        *(ulonglong2*)(cp + 4) = st1;
    }
}

// ---------------- phase B: meta cell + z projections, block-wide (512 thr) ----------
__device__ __forceinline__ void metaB(
    int t, int b,
    const float* __restrict__ Wzx_l, const float* __restrict__ Wzh_l,
    const float* __restrict__ Wzb_l,
    const float* __restrict__ bzx_l, const float* __restrict__ bzh_l, float* smem)
{
    float* sm  = smem;          // 1024
    float* smh = smem + 1024;   // 256
    int tid = threadIdx.x;
    const float* mx = g_Mx + ((long)b * 256 + t) * 1024;
#pragma unroll
    for (int jj = 0; jj < 2; jj++) {
        int j = tid + jj * 512;
        float v = mx[j];
#pragma unroll
        for (int ks = 0; ks < 16; ks++) v += g_mpart[(ks * 64 + b) * 1024 + j];
        sm[j] = v;
    }
    __syncthreads();
    if (tid < 256) {
        int j = tid;
        float mi = sm[j], mf = sm[256 + j], mg = sm[512 + j], mo = sm[768 + j];
        float mco = g_mc[b * 256 + j];
        float mc2 = sigf(mf) * mco + sigf(mi) * tanhf(mg);
        float mh2 = sigf(mo) * tanhf(mc2);
        g_mc[b * 256 + j] = mc2;
        g_Acat[b * 1280 + 1024 + j] = mh2;
        smh[j] = mh2;
    }
    __syncthreads();
    if (tid < 128) {
        int g  = tid >> 5;
        int e0 = (tid & 31) * 2;
        float2 ax = *(const float2*)&bzx_l[g * 64 + e0];
        float2 ah = *(const float2*)&bzh_l[g * 64 + e0];
        float2 ab = make_float2(0.0f, 0.0f);
        const float* wx = Wzx_l + g * 64 + e0;   // stride per m: 256
        const float* wh = Wzh_l + g * 64 + e0;
        const float* wb = Wzb_l + g * 64 + e0;
#pragma unroll 4
        for (int m = 0; m < 256; m++) {
            float mv = smh[m];
            float2 vx = *(const float2*)(wx + m * 256);
            float2 vh = *(const float2*)(wh + m * 256);
            float2 vb = *(const float2*)(wb + m * 256);
            ax.x += mv * vx.x; ax.y += mv * vx.y;
            ah.x += mv * vh.x; ah.y += mv * vh.y;
            ab.x += mv * vb.x; ab.y += mv * vb.y;
        }
        int zo = b * 256 + g * 64 + e0;
        *(float2*)&g_z[0 * 64 * 256 + zo] = ax;
        *(float2*)&g_z[1 * 64 * 256 + zo] = ah;
        *(float2*)&g_z[2 * 64 * 256 + zo] = ab;
    }
    __syncthreads();
}

// ---------------- phase C: d[s][b][g*1024+h] = sum_e z * P, block-wide (512 thr) ----
// tile 64b x 128hh for one (s, g, hhTile); f32x2 inner
__device__ __forceinline__ void dcoefC(
    int item,
    const float* __restrict__ Px_l, const float* __restrict__ Ph_l,
    const float* __restrict__ Pb_l, float* smem)
{
    int hhTile = item & 7;
    int g      = (item >> 3) & 3;
    int s      = item >> 5;               // 0..2
    int hh0    = hhTile * 128;
    float* zs = smem;                     // 64e x 68 (b-major inner)
    float* ps = smem + 64 * 68;           // 64e x 132
    int tid = threadIdx.x;
    const float* P = (s == 0) ? Px_l : ((s == 1) ? Ph_l : Pb_l);
    {   // z -> zs[e][b]
        int lb  = tid >> 3;               // 0..63
        int le0 = (tid & 7) * 8;          // 0..56
        const float* zp = g_z + (s * 64 + lb) * 256 + g * 64 + le0;
#pragma unroll
        for (int q = 0; q < 2; q++) {
            float4 v = *(const float4*)(zp + q * 4);
            zs[(le0 + q * 4 + 0) * 68 + lb] = v.x;
            zs[(le0 + q * 4 + 1) * 68 + lb] = v.y;
            zs[(le0 + q * 4 + 2) * 68 + lb] = v.z;
            zs[(le0 + q * 4 + 3) * 68 + lb] = v.w;
        }
    }
    {   // P -> ps[e][hh]
        int le = tid >> 3;                // 0..63
        int j0 = (tid & 7) * 16;          // 0..112
        const float* pp = P + ((long)g * 64 + le) * 1024 + hh0 + j0;
#pragma unroll
        for (int q = 0; q < 4; q++)
            *(float4*)&ps[le * 132 + j0 + q * 4] = *(const float4*)(pp + q * 4);
    }
    __syncthreads();
    int tb = (tid >> 5) * 4;              // 0..60
    int th = (tid & 31) * 4;              // 0..124
    u64 acc[4][2];
#pragma unroll
    for (int i = 0; i < 4; i++) { acc[i][0] = 0ULL; acc[i][1] = 0ULL; }
#pragma unroll 4
    for (int e = 0; e < 64; e++) {
        float4 zv = *(const float4*)&zs[e * 68 + tb];
        ulonglong2 pv = *(const ulonglong2*)&ps[e * 132 + th];
        u64 s0 = splat2(zv.x), s1 = splat2(zv.y), s2 = splat2(zv.z), s3 = splat2(zv.w);
        acc[0][0] = ffma2(s0, pv.x, acc[0][0]); acc[0][1] = ffma2(s0, pv.y, acc[0][1]);
        acc[1][0] = ffma2(s1, pv.x, acc[1][0]); acc[1][1] = ffma2(s1, pv.y, acc[1][1]);
        acc[2][0] = ffma2(s2, pv.x, acc[2][0]); acc[2][1] = ffma2(s2, pv.y, acc[2][1]);
        acc[3][0] = ffma2(s3, pv.x, acc[3][0]); acc[3][1] = ffma2(s3, pv.y, acc[3][1]);
    }
#pragma unroll
    for (int i = 0; i < 4; i++) {
        ulonglong2 st; st.x = acc[i][0]; st.y = acc[i][1];
        *(ulonglong2*)&g_d[((long)s * 64 + tb + i) * 4096 + g * 1024 + hh0 + th] = st;
    }
    __syncthreads();
}

// ---------------- phase D: combine partials + LSTM cell, block-wide (512 thr) -------
__device__ __forceinline__ void combineD(int t, int w, float* __restrict__ Xout)
{
    int idx = w * 512 + threadIdx.x;      // 0..65535 = 64b x 1024h
    int b  = idx >> 10;
    int hh = idx & 1023;
    long rbase = (long)b * 4096 + hh;
    float pre[4];
#pragma unroll
    for (int g = 0; g < 4; g++) {
        long n = rbase + g * 1024;
        float gh = 0.0f;
#pragma unroll
        for (int ks = 0; ks < 16; ks++) gh += g_gpart[(long)ks * 262144 + n];
        float gx = g_Gx[((long)b * 256 + t) * 4096 + g * 1024 + hh];
        pre[g] = g_d[n] * gx + g_d[262144 + n] * gh + g_d[524288 + n];
    }
    float co = g_c[idx];
    float c2 = sigf(pre[1]) * co + sigf(pre[0]) * tanhf(pre[2]);
    float h2 = sigf(pre[3]) * tanhf(c2);
    g_c[idx] = c2;
    g_Acat[b * 1280 + hh] = h2;
    Xout[((long)b * 256 + t) * 1024 + hh] = h2;
}

// ---------------- persistent recurrence: 148 blocks x 512 thr, 4 warpgroups ---------
__global__ __launch_bounds__(512, 1) void recur_kernel(
    const float* __restrict__ Wh_l,
    const float* __restrict__ Wzx_l, const float* __restrict__ Wzh_l,
    const float* __restrict__ Wzb_l,
    const float* __restrict__ bzx_l, const float* __restrict__ bzh_l,
    const float* __restrict__ Px_l, const float* __restrict__ Ph_l,
    const float* __restrict__ Pb_l,
    float* __restrict__ Xout)
{
    extern __shared__ float dsm[];        // 12800 floats = 51.2 KB
    __shared__ unsigned s_w[4];
    unsigned nb  = gridDim.x;
    unsigned bid = blockIdx.x;
    int tid   = threadIdx.x;
    int grp   = tid >> 7;
    int gtid  = tid & 127;
    int barid = grp + 1;
    unsigned sense = g_gen;               // uniform at entry

    // init state + queues
    if (bid == 0 && tid == 0) { g_q[0] = 0; g_q[1] = 0; }
    for (int i = bid * 512 + tid; i < 64 * 1280; i += nb * 512) g_Acat[i] = 0.0f;
    for (int i = bid * 512 + tid; i < 64 * 1024; i += nb * 512) g_c[i] = 0.0f;
    for (int i = bid * 512 + tid; i < 64 * 256;  i += nb * 512) g_mc[i] = 0.0f;
    gridbar(nb, sense);

    for (int t = 0; t < 256; t++) {
        // reset the other queue for step t+1 (its step t-1 users all passed a barrier)
        if (bid == 0 && tid == 0) g_q[(t + 1) & 1] = 0;

        // Phase A: 640 tiles via work queue; per-warpgroup 64x128 f32x2 GEMM tiles
        {
            float* sm = dsm + grp * 3136;
            for (;;) {
                if (gtid == 0) s_w[grp] = atomicAdd(&g_q[t & 1], 1u);
                BARG(barid);
                unsigned w = s_w[grp];
                if (w >= 640u) break;
                if (w < 512u) {
                    // main h@Wh^T: N=4096 (32 n-tiles), K-split 16 (Ksub 64)
                    skinnyA(Wh_l, 1024, g_gpart, 4096, 64,
                            (int)(w & 31) * 128, (int)(w >> 5), sm, gtid, barid);
                } else {
                    unsigned q = w - 512u;
                    // meta: N=1024 (8 n-tiles), K-split 16 (Ksub 80)
                    skinnyA(g_Wpack, 1280, g_mpart, 1024, 80,
                            (int)(q & 7) * 128, (int)(q >> 3), sm, gtid, barid);
                }
            }
        }
        gridbar(nb, sense);

        // Phase B: meta cell + z (64 items, block-wide)
        if (bid < 64) metaB(t, bid, Wzx_l, Wzh_l, Wzb_l, bzx_l, bzh_l, dsm);
        gridbar(nb, sense);

        // Phase C: d = z @ P (96 items, block-wide)
        if (bid < 96) dcoefC(bid, Px_l, Ph_l, Pb_l, dsm);
        gridbar(nb, sense);

        // Phase D: combine + cell update (128 chunks of 512)
        if (bid < 128) combineD(t, bid, Xout);
        gridbar(nb, sense);
    }
}

// ---------------- host ----------------
extern "C" void kernel_launch(void* const* d_in, const int* in_sizes, int n_in,
                              void* d_out, int out_size)
{
    const float* x   = (const float*)d_in[0];
    const float* Wx  = (const float*)d_in[1];
    const float* Wh  = (const float*)d_in[2];
    const float* Wmx = (const float*)d_in[3];
    const float* Wmh = (const float*)d_in[4];
    const float* bm  = (const float*)d_in[5];
    const float* Wzx = (const float*)d_in[6];
    const float* bzx = (const float*)d_in[7];
    const float* Wzh = (const float*)d_in[8];
    const float* bzh = (const float*)d_in[9];
    const float* Wzb = (const float*)d_in[10];
    const float* Px  = (const float*)d_in[11];
    const float* Ph  = (const float*)d_in[12];
    const float* Pb  = (const float*)d_in[13];

    float *pGx, *pMx, *pX1;
    cudaGetSymbolAddress((void**)&pGx, g_Gx);
    cudaGetSymbolAddress((void**)&pMx, g_Mx);
    cudaGetSymbolAddress((void**)&pX1, g_X1);

    static int smem_set = 0;
    if (!smem_set) {
        cudaFuncSetAttribute(recur_kernel,
                             cudaFuncAttributeMaxDynamicSharedMemorySize, 51200);
        smem_set = 1;
    }

    for (int l = 0; l < 2; l++) {
        const float* Xin  = l ? (const float*)pX1 : x;
        float*       Xout = l ? (float*)d_out : pX1;
        const float* Wmx_l = Wmx + (long)l * 1024 * 2048;
        const float* Wmh_l = Wmh + (long)l * 1024 * 256;
        const float* Wh_l  = Wh  + (long)l * 4096 * 1024;
        const float* Wx_l  = Wx  + (long)l * 4096 * 1024;
        const float* Wzx_l = Wzx + (long)l * 65536;
        const float* Wzh_l = Wzh + (long)l * 65536;
        const float* Wzb_l = Wzb + (long)l * 65536;
        const float* bzx_l = bzx + l * 256;
        const float* bzh_l = bzh + l * 256;
        const float* Px_l  = Px + (long)l * 4 * 64 * 1024;
        const float* Ph_l  = Ph + (long)l * 4 * 64 * 1024;
        const float* Pb_l  = Pb + (long)l * 4 * 64 * 1024;

        pack_meta<<<5120, 256>>>(Wmx_l, Wmh_l);
        sgemm128<<<dim3(32, 128), 256>>>(Xin, Wx_l, 1024, nullptr, pGx, 4096);
        sgemm128<<<dim3(8, 128), 256>>>(Xin, Wmx_l, 2048, bm + l * 1024, pMx, 1024);
        recur_kernel<<<148, 512, 51200>>>(Wh_l, Wzx_l, Wzh_l, Wzb_l, bzx_l, bzh_l,
                                          Px_l, Ph_l, Pb_l, Xout);
    }
}